// round 15
// baseline (speedup 1.0000x reference)
#include <cuda_runtime.h>
#include <cuda_bf16.h>
#include <cstdint>

#define BH   64
#define SEQ  8192
#define HD   128
#define SP   7936
#define KEEP 256
#define KTOP 192
#define LOCQ 64
#define NCHK 31     // SP / 256

// ---------------- scratch (device globals: allocation-free) ----------------
__device__ __align__(128) __nv_bfloat16 g_X [(size_t)BH * SP * 256];   // [head][t][256] (k|v)
__device__ __align__(128) __nv_bfloat16 g_Y0[(size_t)BH * SP * 512];   // [head][t][512]
__device__ __align__(128) __nv_bfloat16 g_L [(size_t)BH * SP * 256];   // [head][t][256]
__device__ __align__(128) __nv_bfloat16 g_A0[512 * 768];               // conv0 W, k = dk*256+c
__device__ __align__(128) __nv_bfloat16 g_A1[256 * 1536];              // conv1 W, k = dk*512+c
__device__ int   g_hh    [BH * KEEP];
__device__ int   g_non   [BH * SP];
__device__ int   g_res   [BH * 256];
__device__ int   g_noninv[BH * SEQ];
__device__ float g_pm [BH * NCHK * 256];
__device__ float g_ps [BH * NCHK * 256];
__device__ float g_rm [BH * 256];
__device__ float g_rs [BH * 256];

// ---------------- helpers ----------------
__device__ __forceinline__ uint32_t smem_u32(const void* p) {
    return (uint32_t)__cvta_generic_to_shared(p);
}
__device__ __forceinline__ void ldsm_x4(uint32_t* r, uint32_t a) {
    asm volatile("ldmatrix.sync.aligned.m8n8.x4.shared.b16 {%0,%1,%2,%3}, [%4];"
                 : "=r"(r[0]), "=r"(r[1]), "=r"(r[2]), "=r"(r[3]) : "r"(a));
}
__device__ __forceinline__ void ldsm_x2(uint32_t* r, uint32_t a) {
    asm volatile("ldmatrix.sync.aligned.m8n8.x2.shared.b16 {%0,%1}, [%2];"
                 : "=r"(r[0]), "=r"(r[1]) : "r"(a));
}
__device__ __forceinline__ void ldsm_x4t(uint32_t* r, uint32_t a) {
    asm volatile("ldmatrix.sync.aligned.m8n8.x4.trans.shared.b16 {%0,%1,%2,%3}, [%4];"
                 : "=r"(r[0]), "=r"(r[1]), "=r"(r[2]), "=r"(r[3]) : "r"(a));
}
__device__ __forceinline__ void ldsm_x2t(uint32_t* r, uint32_t a) {
    asm volatile("ldmatrix.sync.aligned.m8n8.x2.trans.shared.b16 {%0,%1}, [%2];"
                 : "=r"(r[0]), "=r"(r[1]) : "r"(a));
}
__device__ __forceinline__ void mma16816(float* c, const uint32_t* a, const uint32_t* b) {
    asm volatile(
        "mma.sync.aligned.m16n8k16.row.col.f32.bf16.bf16.f32 "
        "{%0,%1,%2,%3}, {%4,%5,%6,%7}, {%8,%9}, {%0,%1,%2,%3};\n"
        : "+f"(c[0]), "+f"(c[1]), "+f"(c[2]), "+f"(c[3])
        : "r"(a[0]), "r"(a[1]), "r"(a[2]), "r"(a[3]), "r"(b[0]), "r"(b[1]));
}
__device__ __forceinline__ void cpa16(uint32_t d, const void* s, int sz) {
    asm volatile("cp.async.cg.shared.global [%0], [%1], 16, %2;"
                 :: "r"(d), "l"(s), "r"(sz));
}
__device__ __forceinline__ void cpa_commit() {
    asm volatile("cp.async.commit_group;");
}
__device__ __forceinline__ float silu_f(float x) { return x / (1.f + __expf(-x)); }

// ---------------- K1: repack conv weights to bf16 im2col ----------------
__global__ void __launch_bounds__(256) prep_weights_kernel(const float* __restrict__ w0,
                                                           const float* __restrict__ w1) {
    int idx = blockIdx.x * 256 + threadIdx.x;
    if (idx < 512 * 768) {
        int o = idx / 768, k = idx % 768, dk = k / 256, c = k % 256;
        g_A0[idx] = __float2bfloat16(w0[(o * 256 + c) * 3 + dk]);
    } else {
        int i2 = idx - 512 * 768;
        if (i2 < 256 * 1536) {
            int o = i2 / 1536, k = i2 % 1536, dk = k / 512, c = k % 512;
            g_A1[i2] = __float2bfloat16(w1[(o * 512 + c) * 3 + dk]);
        }
    }
}

// ---------------- K2: exact selection (radix top-k, jax tie semantics) ------
__device__ void radix_topk(uint32_t* skey, int limit, int K, int* hist,
                           uint32_t* ctl_pref, int* ctl_rem, int* ctl_cnt,
                           uint32_t* p_thr, int* p_cntgt) {
    const int tid = threadIdx.x;
    if (tid == 0) { *ctl_pref = 0u; *ctl_rem = K; *ctl_cnt = 0; }
    __syncthreads();
    for (int shift = 24; shift >= 0; shift -= 8) {
        hist[tid] = 0;
        __syncthreads();
        uint32_t pref  = *ctl_pref;
        uint32_t hmask = (shift == 24) ? 0u : (0xFFFFFFFFu << (shift + 8));
        for (int i = tid; i < limit; i += 256) {
            uint32_t k = skey[i];
            if (((k ^ pref) & hmask) == 0u) atomicAdd(&hist[(k >> shift) & 255], 1);
        }
        __syncthreads();
        if (tid == 0) {
            int accv = 0, b = 255;
            for (; b > 0; b--) {
                if (accv + hist[b] >= *ctl_rem) break;
                accv += hist[b];
            }
            *ctl_pref = pref | ((uint32_t)b << shift);
            *ctl_rem -= accv;
            *ctl_cnt += accv;
        }
        __syncthreads();
    }
    *p_thr = *ctl_pref;
    *p_cntgt = *ctl_cnt;
    __syncthreads();
}

__global__ void __launch_bounds__(256) select_kernel(const float* __restrict__ scores) {
    __shared__ uint32_t      s_key [SEQ];
    __shared__ unsigned char s_mask[SEQ];
    __shared__ int           s_scan[257];
    __shared__ int           s_hist[256];
    __shared__ uint32_t      s_pref;
    __shared__ int           s_rem, s_cnt;

    const int head = blockIdx.x, tid = threadIdx.x;
    const int base = tid * 32;
    const float* sc = scores + (size_t)head * SEQ;
    for (int i = tid; i < SEQ; i += 256) {
        uint32_t b = __float_as_uint(sc[i]);
        s_key[i] = (b & 0x80000000u) ? ~b : (b | 0x80000000u);
        s_mask[i] = 0;
    }
    __syncthreads();

    auto tie_fill = [&](uint32_t thr, int need, int limit) {
        int eqc = 0;
#pragma unroll
        for (int j = 0; j < 32; j++) {
            int i = base + j;
            if (i < limit && s_key[i] == thr) eqc++;
        }
        s_scan[tid] = eqc;
        __syncthreads();
        if (tid == 0) {
            int a = 0;
            for (int k = 0; k < 256; k++) { int t = s_scan[k]; s_scan[k] = a; a += t; }
        }
        __syncthreads();
        int r = s_scan[tid];
        for (int j = 0; j < 32; j++) {
            int i = base + j;
            if (i < limit && s_key[i] == thr) {
                if (r < need) s_mask[i] = 1;
                r++;
            }
        }
        __syncthreads();
    };

    uint32_t thr; int cgt;
    radix_topk(s_key, SEQ - LOCQ, KTOP, s_hist, &s_pref, &s_rem, &s_cnt, &thr, &cgt);
    for (int i = tid; i < SEQ - LOCQ; i += 256)
        if (s_key[i] > thr) s_mask[i] = 1;
    for (int i = SEQ - LOCQ + tid; i < SEQ; i += 256) s_mask[i] = 1;
    __syncthreads();
    tie_fill(thr, KTOP - cgt, SEQ - LOCQ);

    int cnt = 0;
#pragma unroll
    for (int j = 0; j < 32; j++) cnt += s_mask[base + j];
    s_scan[tid] = cnt;
    __syncthreads();
    if (tid == 0) {
        int a = 0;
        for (int k = 0; k < 256; k++) { int t = s_scan[k]; s_scan[k] = a; a += t; }
    }
    __syncthreads();
    {
        int ho = s_scan[tid], no = base - s_scan[tid];
        for (int j = 0; j < 32; j++) {
            int i = base + j;
            if (s_mask[i]) { g_hh[head * KEEP + (ho++)] = i; }
            else { g_noninv[head * SEQ + i] = no; g_non[head * SP + (no++)] = i; }
        }
    }
    __syncthreads();

    for (int i = tid; i < SEQ; i += 256)
        if (s_mask[i]) s_key[i] = 0u;
    __syncthreads();
    uint32_t thr2; int cgt2;
    radix_topk(s_key, SEQ, 256, s_hist, &s_pref, &s_rem, &s_cnt, &thr2, &cgt2);
    for (int i = tid; i < SEQ; i += 256)
        s_mask[i] = (s_key[i] > thr2) ? 1 : 0;
    __syncthreads();
    tie_fill(thr2, 256 - cgt2, SEQ);

    cnt = 0;
#pragma unroll
    for (int j = 0; j < 32; j++) cnt += s_mask[base + j];
    s_scan[tid] = cnt;
    __syncthreads();
    if (tid == 0) {
        int a = 0;
        for (int k = 0; k < 256; k++) { int t = s_scan[k]; s_scan[k] = a; a += t; }
    }
    __syncthreads();
    {
        int ro = s_scan[tid];
        for (int j = 0; j < 32; j++) {
            int i = base + j;
            if (s_mask[i]) g_res[head * 256 + (ro++)] = g_noninv[head * SEQ + i];
        }
    }
}

// ---------------- K3: gather non_k|non_v -> X[t][256] -----------------------
__global__ void __launch_bounds__(256) gather_x_kernel(const float* __restrict__ pk,
                                                       const float* __restrict__ pv) {
    const int head = blockIdx.y;
    const int t0 = blockIdx.x * 128;
    const int tid = threadIdx.x;
    __shared__ int pos[128];
    if (tid < 128) pos[tid] = g_non[head * SP + t0 + tid];
    __syncthreads();
    const int c2 = (tid & 63) * 2;
    const int r4 = tid >> 6;
    for (int r = r4; r < 128; r += 4) {
        size_t src = ((size_t)head * SEQ + pos[r]) * HD + c2;
        float2 vk = *(const float2*)(pk + src);
        float2 vv = *(const float2*)(pv + src);
        __nv_bfloat16* dst = g_X + ((size_t)head * SP + t0 + r) * 256;
        *(__nv_bfloat162*)(dst + c2)       = __nv_bfloat162(__float2bfloat16(vk.x), __float2bfloat16(vk.y));
        *(__nv_bfloat162*)(dst + 128 + c2) = __nv_bfloat162(__float2bfloat16(vv.x), __float2bfloat16(vv.y));
    }
}

// ---------------- K4: exact fp32 hh gather ----------------------------------
__global__ void __launch_bounds__(256) hh_out_kernel(const float* __restrict__ pk,
                                                     const float* __restrict__ pv,
                                                     float* __restrict__ out) {
    const int head = blockIdx.x, tid = threadIdx.x;
    __shared__ int pos[KEEP];
    if (tid < KEEP) pos[tid] = g_hh[head * KEEP + tid];
    __syncthreads();
    const size_t vofs = (size_t)BH * 512 * HD;
    for (int idx = tid; idx < KEEP * HD; idx += 256) {
        int j = idx >> 7, dd = idx & 127;
        size_t src = ((size_t)head * SEQ + pos[j]) * HD + dd;
        size_t dst = ((size_t)head * 512 + j) * HD + dd;
        out[dst] = pk[src];
        out[vofs + dst] = pv[src];
    }
}

// ---------------- K5/K6: conv GEMM 128x256x32, 4-stage ring, warp 64x64 -----
// stage layout: A[128][40] (10240 B) then B[256][40] (20480 B); stride 30720.
template <int CIN, int MTOT>
__global__ void __launch_bounds__(256, 1) conv_gemm_kernel(const float* __restrict__ bias) {
    constexpr int KTOT = 3 * CIN;
    constexpr int NI = KTOT / 32;
    constexpr int NS = 4;
    constexpr int SSTRIDE = 30720;
    const int head = blockIdx.z;
    const int m0 = blockIdx.y * 128;
    const int t0 = blockIdx.x * 256;
    const __nv_bfloat16* __restrict__ A   = (CIN == 256) ? g_A0 : g_A1;
    const __nv_bfloat16* __restrict__ Xh  = ((CIN == 256) ? g_X : g_Y0) + (size_t)head * SP * CIN;
    __nv_bfloat16* __restrict__       Yh  = ((CIN == 256) ? g_Y0 : g_L) + (size_t)head * SP * MTOT;

    extern __shared__ __align__(16) unsigned char sb[];   // 4 * 30720 = 122880 B
    typedef __nv_bfloat16 Row40[40];
    typedef __nv_bfloat16 Row136[136];
    Row136* Cs = (Row136*)sb;             // epilogue alias: [256][136]

    const int tid = threadIdx.x, lane = tid & 31, wid = tid >> 5;
    const int wm = wid >> 2, wn = wid & 3;     // 2 x 4 warps, warp tile 64x64

    float acc[4][8][4];
#pragma unroll
    for (int i = 0; i < 4; i++)
#pragma unroll
        for (int j = 0; j < 8; j++)
#pragma unroll
            for (int k = 0; k < 4; k++) acc[i][j][k] = 0.f;

    auto issue = [&](int it, int s) {
        Row40* As = (Row40*)(sb + s * SSTRIDE);
        Row40* Bs = (Row40*)(sb + s * SSTRIDE + 10240);
        const int dk = (it * 32) / CIN;
        const int cbase = it * 32 - dk * CIN;
#pragma unroll
        for (int j = 0; j < 2; j++) {          // A: 128 rows x 2 x 16B
            int q = tid + j * 256;
            int row = q >> 2, kc = (q & 3) * 8;
            cpa16(smem_u32(&As[row][kc]),
                  A + (size_t)(m0 + row) * KTOT + it * 32 + kc, 16);
        }
#pragma unroll
        for (int j = 0; j < 4; j++) {          // B: 256 t-rows x 4 x 16B
            int q = tid + j * 256;
            int tl = q >> 2, kc = (q & 3) * 8;
            int tg = t0 + tl + dk - 1;         // conv pad 1
            int ok = (tg >= 0 && tg < SP) ? 16 : 0;
            int tc = (tg < 0) ? 0 : ((tg >= SP) ? SP - 1 : tg);
            cpa16(smem_u32(&Bs[tl][kc]),
                  Xh + (size_t)tc * CIN + cbase + kc, ok);
        }
    };

#pragma unroll
    for (int it = 0; it < NS - 1; ++it) { issue(it, it); cpa_commit(); }

    for (int i = 0; i < NI; i++) {
        asm volatile("cp.async.wait_group 2;");
        __syncthreads();
        const int s = i & 3;
        Row40* As = (Row40*)(sb + s * SSTRIDE);
        Row40* Bs = (Row40*)(sb + s * SSTRIDE + 10240);
#pragma unroll
        for (int ks = 0; ks < 2; ks++) {
            const int kr = ks * 16;
            uint32_t af[4][4], bfr[8][2];
#pragma unroll
            for (int mf = 0; mf < 4; mf++)
                ldsm_x4(af[mf], smem_u32(&As[wm * 64 + mf * 16 + (lane & 15)]
                                            [kr + ((lane & 16) ? 8 : 0)]));
#pragma unroll
            for (int nf = 0; nf < 8; nf++)
                ldsm_x2(bfr[nf], smem_u32(&Bs[wn * 64 + nf * 8 + (lane & 7)]
                                             [kr + ((lane & 8) ? 8 : 0)]));
#pragma unroll
            for (int mf = 0; mf < 4; mf++)
#pragma unroll
                for (int nf = 0; nf < 8; nf++)
                    mma16816(acc[mf][nf], af[mf], bfr[nf]);
        }
        int nx = i + NS - 1;
        if (nx < NI) issue(nx, nx & 3);
        cpa_commit();
    }
    asm volatile("cp.async.wait_group 0;");
    __syncthreads();

    // epilogue: bias + SiLU, transpose through smem, vectorized [t][c] store
#pragma unroll
    for (int mf = 0; mf < 4; mf++) {
#pragma unroll
        for (int half = 0; half < 2; half++) {
            int c = wm * 64 + mf * 16 + (lane >> 2) + half * 8;
            float bv = bias[m0 + c];
#pragma unroll
            for (int nf = 0; nf < 8; nf++) {
#pragma unroll
                for (int p = 0; p < 2; p++) {
                    int tl = wn * 64 + nf * 8 + (lane & 3) * 2 + p;
                    Cs[tl][c] = __float2bfloat16(silu_f(acc[mf][nf][half * 2 + p] + bv));
                }
            }
        }
    }
    __syncthreads();
#pragma unroll
    for (int j = 0; j < 16; j++) {
        int q = tid + j * 256;
        int row = q >> 4, col = (q & 15) * 8;
        uint4 v = *(const uint4*)&Cs[row][col];
        *(uint4*)(Yh + (size_t)(t0 + row) * MTOT + m0 + col) = v;
    }
}

// ---------------- K7a/b/c: column-wise softmax over t -----------------------
__global__ void __launch_bounds__(256) smax_partial_kernel() {
    const int head = blockIdx.y, chunk = blockIdx.x, c = threadIdx.x;
    const __nv_bfloat16* base = g_L + ((size_t)head * SP + chunk * 256) * 256 + c;
    float m = -1e30f;
    for (int t = 0; t < 256; t++)
        m = fmaxf(m, __bfloat162float(base[(size_t)t * 256]));
    float s = 0.f;
    for (int t = 0; t < 256; t++)
        s += __expf(__bfloat162float(base[(size_t)t * 256]) - m);
    g_pm[(head * NCHK + chunk) * 256 + c] = m;
    g_ps[(head * NCHK + chunk) * 256 + c] = s;
}

__global__ void __launch_bounds__(256) smax_reduce_kernel(const float* __restrict__ nz) {
    const int head = blockIdx.x, c = threadIdx.x;
    float M = -1e30f;
    for (int j = 0; j < NCHK; j++)
        M = fmaxf(M, g_pm[(head * NCHK + j) * 256 + c]);
    float S = 0.f;
    for (int j = 0; j < NCHK; j++)
        S += g_ps[(head * NCHK + j) * 256 + c] * __expf(g_pm[(head * NCHK + j) * 256 + c] - M);
    g_rm[head * 256 + c] = M;
    g_rs[head * 256 + c] = nz[0] / S;
}

__global__ void __launch_bounds__(256) smax_norm_kernel() {
    const int head = blockIdx.y, t0 = blockIdx.x * 128, c = threadIdx.x;
    const float M = g_rm[head * 256 + c];
    const float sc = g_rs[head * 256 + c];
    __nv_bfloat16* base = g_L + ((size_t)head * SP + t0) * 256 + c;
    for (int r = 0; r < 128; r++) {
        float x = __bfloat162float(base[(size_t)r * 256]);
        base[(size_t)r * 256] = __float2bfloat16(__expf(x - M) * sc);
    }
}

// ---------------- K8: merged GEMM (mma.sync, 4-stage, unchanged R12) -------
__global__ void __launch_bounds__(256, 2) merged_gemm_kernel(float* __restrict__ out) {
    constexpr int NI = SP / 32;
    constexpr int NS = 4;
    const int head = blockIdx.z;
    const int m0 = blockIdx.y * 128;
    const int nsel = blockIdx.x;
    const int nch0 = nsel * 128;
    const __nv_bfloat16* __restrict__ Lh = g_L + (size_t)head * SP * 256;
    const __nv_bfloat16* __restrict__ Xh = g_X + (size_t)head * SP * 256;

    extern __shared__ __align__(16) unsigned char sb[];
    typedef __nv_bfloat16 Row136[136];

    const int tid = threadIdx.x, lane = tid & 31, wid = tid >> 5;
    const int wm = wid >> 2, wn = wid & 3;

    float acc[4][4][4];
#pragma unroll
    for (int i = 0; i < 4; i++)
#pragma unroll
        for (int j = 0; j < 4; j++)
#pragma unroll
            for (int k = 0; k < 4; k++) acc[i][j][k] = 0.f;

    auto issue = [&](int it, int s) {
        Row136* AsT = (Row136*)(sb + s * 17408);
        Row136* Bs  = (Row136*)(sb + s * 17408 + 8704);
        const int k0 = it * 32;
#pragma unroll
        for (int j = 0; j < 2; j++) {
            int q = tid + j * 256;
            int kr = q >> 4, c8 = (q & 15) * 8;
            cpa16(smem_u32(&AsT[kr][c8]), Lh + (size_t)(k0 + kr) * 256 + m0 + c8, 16);
        }
#pragma unroll
        for (int j = 0; j < 2; j++) {
            int q = tid + j * 256;
            int kr = q >> 4, c8 = (q & 15) * 8;
            cpa16(smem_u32(&Bs[kr][c8]), Xh + (size_t)(k0 + kr) * 256 + nch0 + c8, 16);
        }
    };

#pragma unroll
    for (int it = 0; it < NS - 1; ++it) { issue(it, it); cpa_commit(); }

    for (int i = 0; i < NI; i++) {
        asm volatile("cp.async.wait_group 2;");
        __syncthreads();
        const int s = i & 3;
        Row136* AsT = (Row136*)(sb + s * 17408);
        Row136* Bs  = (Row136*)(sb + s * 17408 + 8704);
#pragma unroll
        for (int ks = 0; ks < 2; ks++) {
            const int kr = ks * 16;
            uint32_t af[4][4], bfr[4][2];
#pragma unroll
            for (int mf = 0; mf < 4; mf++)
                ldsm_x4t(af[mf], smem_u32(&AsT[kr + (lane & 7) + ((lane & 16) ? 8 : 0)]
                                              [wm * 64 + mf * 16 + ((lane & 8) ? 8 : 0)]));
#pragma unroll
            for (int nf = 0; nf < 4; nf++)
                ldsm_x2t(bfr[nf], smem_u32(&Bs[kr + (lane & 15)][wn * 32 + nf * 8]));
#pragma unroll
            for (int mf = 0; mf < 4; mf++)
#pragma unroll
                for (int nf = 0; nf < 4; nf++)
                    mma16816(acc[mf][nf], af[mf], bfr[nf]);
        }
        int nx = i + NS - 1;
        if (nx < NI) issue(nx, nx & 3);
        cpa_commit();
    }

    const size_t vofs = (size_t)BH * 512 * HD;
    const size_t hofs = nsel ? vofs : 0;
#pragma unroll
    for (int mf = 0; mf < 4; mf++) {
        int gm = m0 + wm * 64 + mf * 16 + (lane >> 2);
#pragma unroll
        for (int half = 0; half < 2; half++) {
            int r = gm + half * 8;
            float* dst_row = out + hofs + ((size_t)head * 512 + 256 + r) * HD;
#pragma unroll
            for (int nf = 0; nf < 4; nf++) {
                int d = wn * 32 + nf * 8 + (lane & 3) * 2;
                dst_row[d + 0] = acc[mf][nf][half * 2 + 0];
                dst_row[d + 1] = acc[mf][nf][half * 2 + 1];
            }
        }
    }
}

// ---------------- K9: fp32 residual add ------------------------------------
__global__ void __launch_bounds__(256) residual_kernel(const float* __restrict__ pk,
                                                       const float* __restrict__ pv,
                                                       const float* __restrict__ norm,
                                                       float* __restrict__ out) {
    const int head = blockIdx.x, tid = threadIdx.x;
    const float c = 1.f - norm[0];
    const size_t vofs = (size_t)BH * 512 * HD;
    __shared__ int pos[256];
    if (tid < 256) pos[tid] = g_non[head * SP + g_res[head * 256 + tid]];
    __syncthreads();
    for (int idx = tid; idx < 256 * HD; idx += 256) {
        int m = idx >> 7, d = idx & 127;
        size_t src = ((size_t)head * SEQ + pos[m]) * HD + d;
        size_t dst = ((size_t)head * 512 + 256 + m) * HD + d;
        out[dst]        += c * pk[src];
        out[vofs + dst] += c * pv[src];
    }
}

// ---------------- launch ----------------
extern "C" void kernel_launch(void* const* d_in, const int* in_sizes, int n_in,
                              void* d_out, int out_size) {
    const float* pk = (const float*)d_in[0];
    const float* pv = (const float*)d_in[1];
    const float* sc = (const float*)d_in[2];
    const float* w0 = (const float*)d_in[3];
    const float* b0 = (const float*)d_in[4];
    const float* w1 = (const float*)d_in[5];
    const float* b1 = (const float*)d_in[6];
    const float* nz = (const float*)d_in[7];
    float* out = (float*)d_out;

    cudaFuncSetAttribute(conv_gemm_kernel<256, 512>,
                         cudaFuncAttributeMaxDynamicSharedMemorySize, 122880);
    cudaFuncSetAttribute(conv_gemm_kernel<512, 256>,
                         cudaFuncAttributeMaxDynamicSharedMemorySize, 122880);
    cudaFuncSetAttribute(merged_gemm_kernel,
                         cudaFuncAttributeMaxDynamicSharedMemorySize, 69632);

    prep_weights_kernel<<<3072, 256>>>(w0, w1);
    select_kernel<<<64, 256>>>(sc);
    gather_x_kernel<<<dim3(62, 64), 256>>>(pk, pv);
    hh_out_kernel<<<64, 256>>>(pk, pv, out);
    conv_gemm_kernel<256, 512><<<dim3(31, 4, 64), 256, 122880>>>(b0);
    conv_gemm_kernel<512, 256><<<dim3(31, 2, 64), 256, 122880>>>(b1);
    smax_partial_kernel<<<dim3(NCHK, 64), 256>>>();
    smax_reduce_kernel<<<64, 256>>>(nz);
    smax_norm_kernel<<<dim3(62, 64), 256>>>();
    merged_gemm_kernel<<<dim3(2, 2, 64), 256, 69632>>>(out);
    residual_kernel<<<64, 256>>>(pk, pv, nz, out);
}